// round 2
// baseline (speedup 1.0000x reference)
#include <cuda_runtime.h>
#include <cuda_bf16.h>
#include <cstdint>
#include <cstddef>

#define NPATCH 12544
#define PD     3840
#define PROJ   768
#define TOKN   9633792ULL

__device__ float2 g_stats[NPATCH];
__device__ float  g_u[PROJ];
__device__ float  g_v[PROJ];

// ---------------- patch extraction + LN stats ----------------
__global__ void patch_kernel(const float* __restrict__ img, float* __restrict__ patches) {
    int p = blockIdx.x;
    int b = p / 196;
    int pg = p - b * 196;
    int gy = pg / 14, gx = pg - (pg / 14) * 14;
    int t = threadIdx.x;

    float vals[15];
    float s = 0.f, ss = 0.f;
#pragma unroll
    for (int j = 0; j < 15; ++j) {
        int d = t + j * 256;
        int pix = d / 15;
        int r = d - pix * 15;
        int g = r / 3;
        int c = r - g * 3;
        int py = pix >> 4, px = pix & 15;
        int dh = (g == 0) ? 0 : ((g == 1 || g == 3) ? 8 : -8);
        int dw = (g == 0) ? 0 : ((g <= 2) ? 8 : -8);
        int h = gy * 16 + py + dh;
        int w = gx * 16 + px + dw;
        float v = 0.f;
        if ((unsigned)h < 224u && (unsigned)w < 224u)
            v = img[(((size_t)b * 224 + h) * 224 + w) * 3 + c];
        vals[j] = v;
        s += v; ss += v * v;
    }
    float* dst = patches + (size_t)p * PD;
#pragma unroll
    for (int j = 0; j < 15; ++j) dst[t + j * 256] = vals[j];

    // block reduce
#pragma unroll
    for (int o = 16; o > 0; o >>= 1) {
        s  += __shfl_xor_sync(0xffffffffu, s, o);
        ss += __shfl_xor_sync(0xffffffffu, ss, o);
    }
    __shared__ float rs[16];
    int warp = t >> 5, lane = t & 31;
    if (lane == 0) { rs[warp] = s; rs[8 + warp] = ss; }
    __syncthreads();
    if (t == 0) {
        float S = 0.f, SS = 0.f;
#pragma unroll
        for (int w2 = 0; w2 < 8; ++w2) { S += rs[w2]; SS += rs[8 + w2]; }
        float mean = S * (1.f / PD);
        float var = SS * (1.f / PD) - mean * mean;
        g_stats[p] = make_float2(mean, rsqrtf(var + 1e-6f));
    }
}

// ---------------- u/v column sums ----------------
__global__ void zero_uv_kernel() {
    int t = threadIdx.x;
    if (t < PROJ) { g_u[t] = 0.f; g_v[t] = 0.f; }
}

__global__ void uv_kernel(const float* __restrict__ W, const float* __restrict__ gamma,
                          const float* __restrict__ beta) {
    int e = blockIdx.x * 256 + threadIdx.x;
    int d0 = blockIdx.y * 240;
    float u = 0.f, v = 0.f;
#pragma unroll 4
    for (int d = d0; d < d0 + 240; ++d) {
        float w = W[(size_t)d * PROJ + e];
        u += gamma[d] * w;
        v += beta[d] * w;
    }
    atomicAdd(&g_u[e], u);
    atomicAdd(&g_v[e], v);
}

// ---------------- GEMM (tf32 mma.sync) ----------------
#define BM 128
#define BN 256
#define BK 16
#define LDA 20
#define LDB 264
#define KITERS 240
#define SMEM_FLOATS (2*BM*LDA + 2*BK*LDB + 2*16)

__device__ __forceinline__ uint32_t sptr(const void* p) {
    uint32_t a;
    asm("{ .reg .u64 t; cvta.to.shared.u64 t, %1; cvt.u32.u64 %0, t; }" : "=r"(a) : "l"(p));
    return a;
}
__device__ __forceinline__ uint32_t tf32c(float f) {
    uint32_t r;
    asm("cvt.rna.tf32.f32 %0, %1;" : "=r"(r) : "f"(f));
    return r;
}
#define CP16(dst, src) asm volatile("cp.async.cg.shared.global [%0], [%1], 16;" :: "r"(sptr(dst)), "l"(src))
#define MMA8(C, A_, B_) \
    asm volatile("mma.sync.aligned.m16n8k8.row.col.f32.tf32.tf32.f32 " \
                 "{%0,%1,%2,%3},{%4,%5,%6,%7},{%8,%9},{%0,%1,%2,%3};" \
                 : "+f"((C)[0]), "+f"((C)[1]), "+f"((C)[2]), "+f"((C)[3]) \
                 : "r"((A_)[0]), "r"((A_)[1]), "r"((A_)[2]), "r"((A_)[3]), \
                   "r"((B_)[0]), "r"((B_)[1]))

__global__ __launch_bounds__(256, 1)
void gemm_kernel(const float* __restrict__ A, const float* __restrict__ W,
                 const float* __restrict__ gamma, const float* __restrict__ bbias,
                 float* __restrict__ out) {
    extern __shared__ float sm[];
    float* As = sm;                       // [2][BM][LDA]
    float* Bs = sm + 2 * BM * LDA;        // [2][BK][LDB]
    float* Gs = sm + 2 * BM * LDA + 2 * BK * LDB;  // [2][16]

    const int m0 = blockIdx.x * BM;
    const int n0 = blockIdx.y * BN;
    const int t = threadIdx.x;
    const int warp = t >> 5, lane = t & 31;
    const int wm = warp >> 2, wn = warp & 3;
    const int gid = lane >> 2, tig = lane & 3;

    float c[4][8][4];
#pragma unroll
    for (int i = 0; i < 4; ++i)
#pragma unroll
        for (int j = 0; j < 8; ++j)
#pragma unroll
            for (int q = 0; q < 4; ++q) c[i][j][q] = 0.f;

    // stage loader
    auto load_stage = [&](int s, int it) {
        int k0 = it * BK;
        float* as = As + s * BM * LDA;
        const float* ag = A + (size_t)m0 * PD + k0;
#pragma unroll
        for (int q = 0; q < 2; ++q) {
            int cid = t * 2 + q;
            int row = cid >> 2, ch = cid & 3;
            CP16(as + row * LDA + ch * 4, ag + (size_t)row * PD + ch * 4);
        }
        float* bs = Bs + s * BK * LDB;
        const float* bg = W + (size_t)k0 * PROJ + n0;
#pragma unroll
        for (int q = 0; q < 4; ++q) {
            int cid = q * 256 + t;
            int row = cid >> 6, ch = cid & 63;
            CP16(bs + row * LDB + ch * 4, bg + (size_t)row * PROJ + ch * 4);
        }
        if (t < 4) CP16(Gs + s * 16 + t * 4, gamma + k0 + t * 4);
        asm volatile("cp.async.commit_group;");
    };

    auto compute = [&](int s) {
        const float* as = As + s * BM * LDA;
        const float* bs = Bs + s * BK * LDB;
        const float* gs = Gs + s * 16;
#pragma unroll
        for (int kk = 0; kk < 2; ++kk) {
            int kb = kk * 8;
            float ga = gs[kb + tig], gb = gs[kb + tig + 4];
            uint32_t bf[8][2];
#pragma unroll
            for (int j = 0; j < 8; ++j) {
                float x0 = bs[(kb + tig) * LDB + wn * 64 + j * 8 + gid] * ga;
                float x1 = bs[(kb + tig + 4) * LDB + wn * 64 + j * 8 + gid] * gb;
                bf[j][0] = tf32c(x0);
                bf[j][1] = tf32c(x1);
            }
            uint32_t af[4][4];
#pragma unroll
            for (int i = 0; i < 4; ++i) {
                const float* ap = as + (wm * 64 + i * 16 + gid) * LDA;
                af[i][0] = tf32c(ap[kb + tig]);
                af[i][1] = tf32c(ap[8 * LDA + kb + tig]);
                af[i][2] = tf32c(ap[kb + tig + 4]);
                af[i][3] = tf32c(ap[8 * LDA + kb + tig + 4]);
            }
#pragma unroll
            for (int i = 0; i < 4; ++i)
#pragma unroll
                for (int j = 0; j < 8; ++j) MMA8(c[i][j], af[i], bf[j]);
        }
    };

    load_stage(0, 0);
    for (int it = 0; it < KITERS; ++it) {
        if (it < KITERS - 1) {
            load_stage((it + 1) & 1, it + 1);
            asm volatile("cp.async.wait_group 1;");
        } else {
            asm volatile("cp.async.wait_group 0;");
        }
        __syncthreads();
        compute(it & 1);
        __syncthreads();
    }

    // epilogue: token = rstd*S + (-rstd*mean)*u + (v + b)
    float ue[8][2], vb[8][2];
#pragma unroll
    for (int j = 0; j < 8; ++j) {
        int e = n0 + wn * 64 + j * 8 + tig * 2;
        ue[j][0] = g_u[e];     ue[j][1] = g_u[e + 1];
        vb[j][0] = g_v[e] + bbias[e];
        vb[j][1] = g_v[e + 1] + bbias[e + 1];
    }
#pragma unroll
    for (int i = 0; i < 4; ++i) {
        int mrow = m0 + wm * 64 + i * 16 + gid;
        float2 s0 = g_stats[mrow];
        float2 s1 = g_stats[mrow + 8];
        float r0 = s0.y, mm0 = -s0.x * s0.y;
        float r1 = s1.y, mm1 = -s1.x * s1.y;
#pragma unroll
        for (int j = 0; j < 8; ++j) {
            int e = n0 + wn * 64 + j * 8 + tig * 2;
            float* o0 = out + (size_t)mrow * PROJ + e;
            float* o1 = out + (size_t)(mrow + 8) * PROJ + e;
            o0[0] = r0 * c[i][j][0] + mm0 * ue[j][0] + vb[j][0];
            o0[1] = r0 * c[i][j][1] + mm0 * ue[j][1] + vb[j][1];
            o1[0] = r1 * c[i][j][2] + mm1 * ue[j][0] + vb[j][0];
            o1[1] = r1 * c[i][j][3] + mm1 * ue[j][1] + vb[j][1];
        }
    }
}

// ---------------- launch ----------------
extern "C" void kernel_launch(void* const* d_in, const int* in_sizes, int n_in,
                              void* d_out, int out_size) {
    const float* images = (const float*)d_in[0];
    const float* gamma  = (const float*)d_in[1];
    const float* beta   = (const float*)d_in[2];
    const float* W      = (const float*)d_in[3];
    const float* b      = (const float*)d_in[4];
    float* out = (float*)d_out;
    float* tokens  = out;
    float* patches = out + TOKN;

    patch_kernel<<<NPATCH, 256>>>(images, patches);
    zero_uv_kernel<<<1, 768>>>();
    uv_kernel<<<dim3(3, 16), 256>>>(W, gamma, beta);

    static bool configured = false;
    if (!configured) {
        cudaFuncSetAttribute(gemm_kernel, cudaFuncAttributeMaxDynamicSharedMemorySize,
                             SMEM_FLOATS * sizeof(float));
        configured = true;
    }
    gemm_kernel<<<dim3(98, 3), 256, SMEM_FLOATS * sizeof(float)>>>(patches, W, gamma, b, tokens);
}

// round 4
// speedup vs baseline: 1.0695x; 1.0695x over previous
#include <cuda_runtime.h>
#include <cuda_bf16.h>
#include <cstdint>
#include <cstddef>

#define NPATCH 12544
#define PD     3840
#define PROJ   768
#define TOKN   9633792ULL

__device__ float2 g_stats[NPATCH];
__device__ float  g_u[PROJ];
__device__ float  g_v[PROJ];
__device__ float  g_Wg[(size_t)PD * PROJ];   // rna_tf32(gamma[k] * W[k][e]), same layout as W

// ---------------- patch extraction + LN stats ----------------
__global__ void patch_kernel(const float* __restrict__ img, float* __restrict__ patches) {
    int p = blockIdx.x;
    int b = p / 196;
    int pg = p - b * 196;
    int gy = pg / 14, gx = pg - (pg / 14) * 14;
    int t = threadIdx.x;

    float vals[15];
    float s = 0.f, ss = 0.f;
#pragma unroll
    for (int j = 0; j < 15; ++j) {
        int d = t + j * 256;
        int pix = d / 15;
        int r = d - pix * 15;
        int g = r / 3;
        int c = r - g * 3;
        int py = pix >> 4, px = pix & 15;
        int dh = (g == 0) ? 0 : ((g == 1 || g == 3) ? 8 : -8);
        int dw = (g == 0) ? 0 : ((g <= 2) ? 8 : -8);
        int h = gy * 16 + py + dh;
        int w = gx * 16 + px + dw;
        float v = 0.f;
        if ((unsigned)h < 224u && (unsigned)w < 224u)
            v = img[(((size_t)b * 224 + h) * 224 + w) * 3 + c];
        vals[j] = v;
        s += v; ss += v * v;
    }
    float* dst = patches + (size_t)p * PD;
#pragma unroll
    for (int j = 0; j < 15; ++j) dst[t + j * 256] = vals[j];

#pragma unroll
    for (int o = 16; o > 0; o >>= 1) {
        s  += __shfl_xor_sync(0xffffffffu, s, o);
        ss += __shfl_xor_sync(0xffffffffu, ss, o);
    }
    __shared__ float rs[16];
    int warp = t >> 5, lane = t & 31;
    if (lane == 0) { rs[warp] = s; rs[8 + warp] = ss; }
    __syncthreads();
    if (t == 0) {
        float S = 0.f, SS = 0.f;
#pragma unroll
        for (int w2 = 0; w2 < 8; ++w2) { S += rs[w2]; SS += rs[8 + w2]; }
        float mean = S * (1.f / PD);
        float var = SS * (1.f / PD) - mean * mean;
        g_stats[p] = make_float2(mean, rsqrtf(var + 1e-6f));
    }
}

// ---------------- u/v column sums ----------------
__global__ void zero_uv_kernel() {
    int t = threadIdx.x;
    if (t < PROJ) { g_u[t] = 0.f; g_v[t] = 0.f; }
}

__global__ void uv_kernel(const float* __restrict__ W, const float* __restrict__ gamma,
                          const float* __restrict__ beta) {
    int e = blockIdx.x * 256 + threadIdx.x;
    int d0 = blockIdx.y * 240;
    float u = 0.f, v = 0.f;
#pragma unroll 4
    for (int d = d0; d < d0 + 240; ++d) {
        float w = W[(size_t)d * PROJ + e];
        u += gamma[d] * w;
        v += beta[d] * w;
    }
    atomicAdd(&g_u[e], u);
    atomicAdd(&g_v[e], v);
}

// ---------------- pre-scale + tf32-round W ----------------
__device__ __forceinline__ uint32_t tf32rna(float f) {
    uint32_t r;
    asm("cvt.rna.tf32.f32 %0, %1;" : "=r"(r) : "f"(f));
    return r;
}

__global__ void wg_kernel(const float* __restrict__ W, const float* __restrict__ gamma) {
    size_t i = (size_t)blockIdx.x * 256 + threadIdx.x;   // over 737280 float4s
    float4 w = ((const float4*)W)[i];
    int k = (int)(i / 192);                              // 768/4 float4 per row
    float g = gamma[k];
    w.x = __uint_as_float(tf32rna(w.x * g));
    w.y = __uint_as_float(tf32rna(w.y * g));
    w.z = __uint_as_float(tf32rna(w.z * g));
    w.w = __uint_as_float(tf32rna(w.w * g));
    ((float4*)g_Wg)[i] = w;
}

// ---------------- GEMM (tf32 mma.sync) ----------------
#define BM 128
#define BN 256
#define BK 16
#define LDA 20
#define LDB 264
#define KITERS 240
#define SMEM_FLOATS (2*BM*LDA + 2*BK*LDB)

__device__ __forceinline__ uint32_t sptr(const void* p) {
    uint32_t a;
    asm("{ .reg .u64 t; cvta.to.shared.u64 t, %1; cvt.u32.u64 %0, t; }" : "=r"(a) : "l"(p));
    return a;
}
#define CP16(dst, src) asm volatile("cp.async.cg.shared.global [%0], [%1], 16;" :: "r"(sptr(dst)), "l"(src))
#define MMA8(C, A_, B_) \
    asm volatile("mma.sync.aligned.m16n8k8.row.col.f32.tf32.tf32.f32 " \
                 "{%0,%1,%2,%3},{%4,%5,%6,%7},{%8,%9},{%0,%1,%2,%3};" \
                 : "+f"((C)[0]), "+f"((C)[1]), "+f"((C)[2]), "+f"((C)[3]) \
                 : "r"((A_)[0]), "r"((A_)[1]), "r"((A_)[2]), "r"((A_)[3]), \
                   "r"((B_)[0]), "r"((B_)[1]))

__global__ __launch_bounds__(256, 1)
void gemm_kernel(const float* __restrict__ A, const float* __restrict__ bbias,
                 float* __restrict__ out) {
    extern __shared__ float sm[];
    float* As = sm;                       // [2][BM][LDA]
    float* Bs = sm + 2 * BM * LDA;        // [2][BK][LDB]

    const int m0 = blockIdx.x * BM;
    const int n0 = blockIdx.y * BN;
    const int t = threadIdx.x;
    const int warp = t >> 5, lane = t & 31;
    const int wm = warp >> 2, wn = warp & 3;
    const int gid = lane >> 2, tig = lane & 3;

    float c[4][8][4];
#pragma unroll
    for (int i = 0; i < 4; ++i)
#pragma unroll
        for (int j = 0; j < 8; ++j)
#pragma unroll
            for (int q = 0; q < 4; ++q) c[i][j][q] = 0.f;

    auto load_stage = [&](int s, int it) {
        int k0 = it * BK;
        float* as = As + s * BM * LDA;
        const float* ag = A + (size_t)m0 * PD + k0;
#pragma unroll
        for (int q = 0; q < 2; ++q) {
            int cid = t * 2 + q;
            int row = cid >> 2, ch = cid & 3;
            CP16(as + row * LDA + ch * 4, ag + (size_t)row * PD + ch * 4);
        }
        float* bs = Bs + s * BK * LDB;
        const float* bg = g_Wg + (size_t)k0 * PROJ + n0;
#pragma unroll
        for (int q = 0; q < 4; ++q) {
            int cid = q * 256 + t;
            int row = cid >> 6, ch = cid & 63;
            CP16(bs + row * LDB + ch * 4, bg + (size_t)row * PROJ + ch * 4);
        }
        asm volatile("cp.async.commit_group;");
    };

    auto compute = [&](int s) {
        const float* as = As + s * BM * LDA;
        const uint32_t* bs = (const uint32_t*)(Bs + s * BK * LDB);
#pragma unroll
        for (int kk = 0; kk < 2; ++kk) {
            int kb = kk * 8;
            uint32_t bf[8][2];
#pragma unroll
            for (int j = 0; j < 8; ++j) {
                bf[j][0] = bs[(kb + tig) * LDB + wn * 64 + j * 8 + gid];
                bf[j][1] = bs[(kb + tig + 4) * LDB + wn * 64 + j * 8 + gid];
            }
            uint32_t af[4][4];
#pragma unroll
            for (int i = 0; i < 4; ++i) {
                const float* ap = as + (wm * 64 + i * 16 + gid) * LDA;
                af[i][0] = tf32rna(ap[kb + tig]);
                af[i][1] = tf32rna(ap[8 * LDA + kb + tig]);
                af[i][2] = tf32rna(ap[kb + tig + 4]);
                af[i][3] = tf32rna(ap[8 * LDA + kb + tig + 4]);
            }
#pragma unroll
            for (int i = 0; i < 4; ++i)
#pragma unroll
                for (int j = 0; j < 8; ++j) MMA8(c[i][j], af[i], bf[j]);
        }
    };

    load_stage(0, 0);
    for (int it = 0; it < KITERS; ++it) {
        if (it < KITERS - 1) {
            load_stage((it + 1) & 1, it + 1);
            asm volatile("cp.async.wait_group 1;");
        } else {
            asm volatile("cp.async.wait_group 0;");
        }
        __syncthreads();
        compute(it & 1);
        __syncthreads();
    }

    float ue[8][2], vb[8][2];
#pragma unroll
    for (int j = 0; j < 8; ++j) {
        int e = n0 + wn * 64 + j * 8 + tig * 2;
        ue[j][0] = g_u[e];     ue[j][1] = g_u[e + 1];
        vb[j][0] = g_v[e] + bbias[e];
        vb[j][1] = g_v[e + 1] + bbias[e + 1];
    }
#pragma unroll
    for (int i = 0; i < 4; ++i) {
        int mrow = m0 + wm * 64 + i * 16 + gid;
        float2 s0 = g_stats[mrow];
        float2 s1 = g_stats[mrow + 8];
        float r0 = s0.y, mm0 = -s0.x * s0.y;
        float r1 = s1.y, mm1 = -s1.x * s1.y;
#pragma unroll
        for (int j = 0; j < 8; ++j) {
            int e = n0 + wn * 64 + j * 8 + tig * 2;
            float* o0 = out + (size_t)mrow * PROJ + e;
            float* o1 = out + (size_t)(mrow + 8) * PROJ + e;
            o0[0] = r0 * c[i][j][0] + mm0 * ue[j][0] + vb[j][0];
            o0[1] = r0 * c[i][j][1] + mm0 * ue[j][1] + vb[j][1];
            o1[0] = r1 * c[i][j][2] + mm1 * ue[j][0] + vb[j][0];
            o1[1] = r1 * c[i][j][3] + mm1 * ue[j][1] + vb[j][1];
        }
    }
}

// ---------------- launch ----------------
extern "C" void kernel_launch(void* const* d_in, const int* in_sizes, int n_in,
                              void* d_out, int out_size) {
    const float* images = (const float*)d_in[0];
    const float* gamma  = (const float*)d_in[1];
    const float* beta   = (const float*)d_in[2];
    const float* W      = (const float*)d_in[3];
    const float* b      = (const float*)d_in[4];
    float* out = (float*)d_out;
    float* tokens  = out;
    float* patches = out + TOKN;

    patch_kernel<<<NPATCH, 256>>>(images, patches);
    zero_uv_kernel<<<1, 768>>>();
    uv_kernel<<<dim3(3, 16), 256>>>(W, gamma, beta);
    wg_kernel<<<2880, 256>>>(W, gamma);

    static bool configured = false;
    if (!configured) {
        cudaFuncSetAttribute(gemm_kernel, cudaFuncAttributeMaxDynamicSharedMemorySize,
                             SMEM_FLOATS * sizeof(float));
        configured = true;
    }
    gemm_kernel<<<dim3(98, 3), 256, SMEM_FLOATS * sizeof(float)>>>(patches, b, tokens);
}

// round 5
// speedup vs baseline: 1.7662x; 1.6515x over previous
#include <cuda_runtime.h>
#include <cuda_fp16.h>
#include <cstdint>
#include <cstddef>

#define NPATCH 12544
#define PD     3840
#define PROJ   768
#define TOKN   9633792ULL

__device__ float2 g_stats[NPATCH];
__device__ float  g_u[PROJ];
__device__ float  g_v[PROJ];
__device__ __half g_Ah[(size_t)NPATCH * PD];   // fp16 copy of patches
__device__ __half g_Wh[(size_t)PD * PROJ];     // fp16(gamma[k] * W[k][e])

// ---------------- patch extraction + LN stats + fp16 copy ----------------
__global__ void patch_kernel(const float* __restrict__ img, float* __restrict__ patches) {
    int p = blockIdx.x;
    int b = p / 196;
    int pg = p - b * 196;
    int gy = pg / 14, gx = pg - (pg / 14) * 14;
    int t = threadIdx.x;

    float vals[15];
    float s = 0.f, ss = 0.f;
#pragma unroll
    for (int j = 0; j < 15; ++j) {
        int d = t + j * 256;
        int pix = d / 15;
        int r = d - pix * 15;
        int g = r / 3;
        int c = r - g * 3;
        int py = pix >> 4, px = pix & 15;
        int dh = (g == 0) ? 0 : ((g == 1 || g == 3) ? 8 : -8);
        int dw = (g == 0) ? 0 : ((g <= 2) ? 8 : -8);
        int h = gy * 16 + py + dh;
        int w = gx * 16 + px + dw;
        float v = 0.f;
        if ((unsigned)h < 224u && (unsigned)w < 224u)
            v = img[(((size_t)b * 224 + h) * 224 + w) * 3 + c];
        vals[j] = v;
        s += v; ss += v * v;
    }
    float*  dst  = patches + (size_t)p * PD;
    __half* dsth = g_Ah   + (size_t)p * PD;
#pragma unroll
    for (int j = 0; j < 15; ++j) {
        dst[t + j * 256]  = vals[j];
        dsth[t + j * 256] = __float2half_rn(vals[j]);
    }

#pragma unroll
    for (int o = 16; o > 0; o >>= 1) {
        s  += __shfl_xor_sync(0xffffffffu, s, o);
        ss += __shfl_xor_sync(0xffffffffu, ss, o);
    }
    __shared__ float rs[16];
    int warp = t >> 5, lane = t & 31;
    if (lane == 0) { rs[warp] = s; rs[8 + warp] = ss; }
    __syncthreads();
    if (t == 0) {
        float S = 0.f, SS = 0.f;
#pragma unroll
        for (int w2 = 0; w2 < 8; ++w2) { S += rs[w2]; SS += rs[8 + w2]; }
        float mean = S * (1.f / PD);
        float var = SS * (1.f / PD) - mean * mean;
        g_stats[p] = make_float2(mean, rsqrtf(var + 1e-6f));
    }
}

// ---------------- u/v column sums ----------------
__global__ void zero_uv_kernel() {
    int t = threadIdx.x;
    if (t < PROJ) { g_u[t] = 0.f; g_v[t] = 0.f; }
}

__global__ void uv_kernel(const float* __restrict__ W, const float* __restrict__ gamma,
                          const float* __restrict__ beta) {
    int e = blockIdx.x * 256 + threadIdx.x;
    int d0 = blockIdx.y * 240;
    float u = 0.f, v = 0.f;
#pragma unroll 4
    for (int d = d0; d < d0 + 240; ++d) {
        float w = W[(size_t)d * PROJ + e];
        u += gamma[d] * w;
        v += beta[d] * w;
    }
    atomicAdd(&g_u[e], u);
    atomicAdd(&g_v[e], v);
}

// ---------------- gamma-scale W -> fp16 ----------------
__global__ void wg_kernel(const float* __restrict__ W, const float* __restrict__ gamma) {
    size_t i = (size_t)blockIdx.x * 256 + threadIdx.x;   // over 737280 float4s
    float4 w = ((const float4*)W)[i];
    int k = (int)(i / 192);                              // 192 float4 per K-row
    float g = gamma[k];
    __half2 h0 = __floats2half2_rn(w.x * g, w.y * g);
    __half2 h1 = __floats2half2_rn(w.z * g, w.w * g);
    ((__half2*)g_Wh)[i * 2]     = h0;
    ((__half2*)g_Wh)[i * 2 + 1] = h1;
}

// ---------------- GEMM (fp16 mma.sync m16n8k16 + ldmatrix) ----------------
#define BM 128
#define BN 256
#define BK 32
#define KITERS 120
#define LDA_H 40      // halves per A row (80B, conflict-free ldmatrix phases)
#define LDB_H 264     // halves per B row (528B)
#define SA_BYTES (BM * LDA_H * 2)     // 10240
#define SB_BYTES (BK * LDB_H * 2)     // 16896
#define SMEM_BYTES (2 * (SA_BYTES + SB_BYTES))

__device__ __forceinline__ uint32_t sptr(const void* p) {
    uint32_t a;
    asm("{ .reg .u64 t; cvta.to.shared.u64 t, %1; cvt.u32.u64 %0, t; }" : "=r"(a) : "l"(p));
    return a;
}
#define CP16(dst_u32, src) asm volatile("cp.async.cg.shared.global [%0], [%1], 16;" :: "r"(dst_u32), "l"(src))

#define LDSM4(r0, r1, r2, r3, a) \
    asm volatile("ldmatrix.sync.aligned.m8n8.x4.shared.b16 {%0,%1,%2,%3}, [%4];" \
                 : "=r"(r0), "=r"(r1), "=r"(r2), "=r"(r3) : "r"(a))
#define LDSM4T(r0, r1, r2, r3, a) \
    asm volatile("ldmatrix.sync.aligned.m8n8.x4.trans.shared.b16 {%0,%1,%2,%3}, [%4];" \
                 : "=r"(r0), "=r"(r1), "=r"(r2), "=r"(r3) : "r"(a))

#define MMA16(C, A_, b0_, b1_) \
    asm volatile("mma.sync.aligned.m16n8k16.row.col.f32.f16.f16.f32 " \
                 "{%0,%1,%2,%3},{%4,%5,%6,%7},{%8,%9},{%0,%1,%2,%3};" \
                 : "+f"((C)[0]), "+f"((C)[1]), "+f"((C)[2]), "+f"((C)[3]) \
                 : "r"((A_)[0]), "r"((A_)[1]), "r"((A_)[2]), "r"((A_)[3]), \
                   "r"(b0_), "r"(b1_))

__global__ __launch_bounds__(256, 1)
void gemm_kernel(const float* __restrict__ bbias, float* __restrict__ out) {
    extern __shared__ char smem[];
    const uint32_t sa_base = sptr(smem);                       // [2][BM][LDA_H] halves
    const uint32_t sb_base = sa_base + 2 * SA_BYTES;           // [2][BK][LDB_H] halves

    const int m0 = blockIdx.x * BM;
    const int n0 = blockIdx.y * BN;
    const int t = threadIdx.x;
    const int warp = t >> 5, lane = t & 31;
    const int wm = warp >> 2, wn = warp & 3;     // warp tile: 64m x 64n
    const int gid = lane >> 2, tig = lane & 3;

    float c[4][8][4];
#pragma unroll
    for (int i = 0; i < 4; ++i)
#pragma unroll
        for (int j = 0; j < 8; ++j)
#pragma unroll
            for (int q = 0; q < 4; ++q) c[i][j][q] = 0.f;

    const __half* Ap = g_Ah + (size_t)m0 * PD;
    const __half* Bp = g_Wh + n0;

    auto load_stage = [&](int s, int it) {
        const int k0 = it * BK;
        const uint32_t sa = sa_base + s * SA_BYTES;
        const uint32_t sb = sb_base + s * SB_BYTES;
        // A: 128 rows x 64B = 512 chunks
#pragma unroll
        for (int q = 0; q < 2; ++q) {
            int cid = q * 256 + t;
            int row = cid >> 2, c4 = cid & 3;
            CP16(sa + row * (LDA_H * 2) + c4 * 16,
                 Ap + (size_t)row * PD + k0 + c4 * 8);
        }
        // B: 32 rows x 512B = 1024 chunks
#pragma unroll
        for (int q = 0; q < 4; ++q) {
            int cid = q * 256 + t;
            int row = cid >> 5, c16 = cid & 31;
            CP16(sb + row * (LDB_H * 2) + c16 * 16,
                 Bp + (size_t)(k0 + row) * PROJ + c16 * 8);
        }
        asm volatile("cp.async.commit_group;");
    };

    const int jmat = lane >> 3;       // 0..3: ldmatrix matrix id
    const int rrow = lane & 7;

    auto compute = [&](int s) {
        const uint32_t sa = sa_base + s * SA_BYTES;
        const uint32_t sb = sb_base + s * SB_BYTES;
#pragma unroll
        for (int kk = 0; kk < 2; ++kk) {
            const int kb = kk * 16;
            // A fragments: 4 x ldmatrix.x4  (m16 x k16 each)
            uint32_t af[4][4];
#pragma unroll
            for (int i = 0; i < 4; ++i) {
                int row = wm * 64 + i * 16 + (jmat & 1) * 8 + rrow;
                int col = kb + (jmat >> 1) * 8;
                LDSM4(af[i][0], af[i][1], af[i][2], af[i][3],
                      sa + row * (LDA_H * 2) + col * 2);
            }
            // B fragments + MMA: 4 x ldmatrix.x4.trans (k16 x n16 each -> two n8 tiles)
#pragma unroll
            for (int p = 0; p < 4; ++p) {
                uint32_t b0, b1, b2, b3;
                int row = kb + (jmat & 1) * 8 + rrow;
                int col = wn * 64 + p * 16 + (jmat >> 1) * 8;
                LDSM4T(b0, b1, b2, b3, sb + row * (LDB_H * 2) + col * 2);
#pragma unroll
                for (int i = 0; i < 4; ++i) {
                    MMA16(c[i][2 * p],     af[i], b0, b1);
                    MMA16(c[i][2 * p + 1], af[i], b2, b3);
                }
            }
        }
    };

    load_stage(0, 0);
    for (int it = 0; it < KITERS; ++it) {
        if (it < KITERS - 1) {
            load_stage((it + 1) & 1, it + 1);
            asm volatile("cp.async.wait_group 1;");
        } else {
            asm volatile("cp.async.wait_group 0;");
        }
        __syncthreads();
        compute(it & 1);
        __syncthreads();
    }

    // epilogue: token = rstd*S + (-rstd*mean)*u + (v + b)
    float ue[8][2], vb[8][2];
#pragma unroll
    for (int j = 0; j < 8; ++j) {
        int e = n0 + wn * 64 + j * 8 + tig * 2;
        ue[j][0] = g_u[e];     ue[j][1] = g_u[e + 1];
        vb[j][0] = g_v[e] + bbias[e];
        vb[j][1] = g_v[e + 1] + bbias[e + 1];
    }
#pragma unroll
    for (int i = 0; i < 4; ++i) {
        int mrow = m0 + wm * 64 + i * 16 + gid;
        float2 s0 = g_stats[mrow];
        float2 s1 = g_stats[mrow + 8];
        float r0 = s0.y, mm0 = -s0.x * s0.y;
        float r1 = s1.y, mm1 = -s1.x * s1.y;
#pragma unroll
        for (int j = 0; j < 8; ++j) {
            int e = n0 + wn * 64 + j * 8 + tig * 2;
            float* o0 = out + (size_t)mrow * PROJ + e;
            float* o1 = out + (size_t)(mrow + 8) * PROJ + e;
            o0[0] = r0 * c[i][j][0] + mm0 * ue[j][0] + vb[j][0];
            o0[1] = r0 * c[i][j][1] + mm0 * ue[j][1] + vb[j][1];
            o1[0] = r1 * c[i][j][2] + mm1 * ue[j][0] + vb[j][0];
            o1[1] = r1 * c[i][j][3] + mm1 * ue[j][1] + vb[j][1];
        }
    }
}

// ---------------- launch ----------------
extern "C" void kernel_launch(void* const* d_in, const int* in_sizes, int n_in,
                              void* d_out, int out_size) {
    const float* images = (const float*)d_in[0];
    const float* gamma  = (const float*)d_in[1];
    const float* beta   = (const float*)d_in[2];
    const float* W      = (const float*)d_in[3];
    const float* b      = (const float*)d_in[4];
    float* out = (float*)d_out;
    float* tokens  = out;
    float* patches = out + TOKN;

    patch_kernel<<<NPATCH, 256>>>(images, patches);
    zero_uv_kernel<<<1, 768>>>();
    uv_kernel<<<dim3(3, 16), 256>>>(W, gamma, beta);
    wg_kernel<<<2880, 256>>>(W, gamma);

    static bool configured = false;
    if (!configured) {
        cudaFuncSetAttribute(gemm_kernel, cudaFuncAttributeMaxDynamicSharedMemorySize, SMEM_BYTES);
        configured = true;
    }
    gemm_kernel<<<dim3(98, 3), 256, SMEM_BYTES>>>(b, tokens);
}

// round 6
// speedup vs baseline: 1.7901x; 1.0135x over previous
#include <cuda_runtime.h>
#include <cuda_fp16.h>
#include <cstdint>
#include <cstddef>

#define NPATCH 12544
#define PD     3840
#define PROJ   768
#define TOKN   9633792ULL

__device__ float2 g_stats[NPATCH];
__device__ float  g_u[PROJ];
__device__ float  g_v[PROJ];
__device__ __half g_Ah[(size_t)NPATCH * PD];   // fp16 copy of patches
__device__ __half g_Wh[(size_t)PD * PROJ];     // fp16(gamma[k] * W[k][e])

// ---------------- patch extraction + LN stats + fp16 copy ----------------
__global__ void patch_kernel(const float* __restrict__ img, float* __restrict__ patches) {
    int p = blockIdx.x;
    int b = p / 196;
    int pg = p - b * 196;
    int gy = pg / 14, gx = pg - (pg / 14) * 14;
    int t = threadIdx.x;

    float vals[15];
    float s = 0.f, ss = 0.f;
#pragma unroll
    for (int j = 0; j < 15; ++j) {
        int d = t + j * 256;
        int pix = d / 15;
        int r = d - pix * 15;
        int g = r / 3;
        int c = r - g * 3;
        int py = pix >> 4, px = pix & 15;
        int dh = (g == 0) ? 0 : ((g == 1 || g == 3) ? 8 : -8);
        int dw = (g == 0) ? 0 : ((g <= 2) ? 8 : -8);
        int h = gy * 16 + py + dh;
        int w = gx * 16 + px + dw;
        float v = 0.f;
        if ((unsigned)h < 224u && (unsigned)w < 224u)
            v = img[(((size_t)b * 224 + h) * 224 + w) * 3 + c];
        vals[j] = v;
        s += v; ss += v * v;
    }
    float*  dst  = patches + (size_t)p * PD;
    __half* dsth = g_Ah   + (size_t)p * PD;
#pragma unroll
    for (int j = 0; j < 15; ++j) {
        dst[t + j * 256]  = vals[j];
        dsth[t + j * 256] = __float2half_rn(vals[j]);
    }

#pragma unroll
    for (int o = 16; o > 0; o >>= 1) {
        s  += __shfl_xor_sync(0xffffffffu, s, o);
        ss += __shfl_xor_sync(0xffffffffu, ss, o);
    }
    __shared__ float rs[16];
    int warp = t >> 5, lane = t & 31;
    if (lane == 0) { rs[warp] = s; rs[8 + warp] = ss; }
    __syncthreads();
    if (t == 0) {
        float S = 0.f, SS = 0.f;
#pragma unroll
        for (int w2 = 0; w2 < 8; ++w2) { S += rs[w2]; SS += rs[8 + w2]; }
        float mean = S * (1.f / PD);
        float var = SS * (1.f / PD) - mean * mean;
        g_stats[p] = make_float2(mean, rsqrtf(var + 1e-6f));
    }
}

// ---------------- u/v column sums ----------------
__global__ void zero_uv_kernel() {
    int t = threadIdx.x;
    if (t < PROJ) { g_u[t] = 0.f; g_v[t] = 0.f; }
}

__global__ void uv_kernel(const float* __restrict__ W, const float* __restrict__ gamma,
                          const float* __restrict__ beta) {
    int e = blockIdx.x * 256 + threadIdx.x;
    int d0 = blockIdx.y * 240;
    float u = 0.f, v = 0.f;
#pragma unroll 4
    for (int d = d0; d < d0 + 240; ++d) {
        float w = W[(size_t)d * PROJ + e];
        u += gamma[d] * w;
        v += beta[d] * w;
    }
    atomicAdd(&g_u[e], u);
    atomicAdd(&g_v[e], v);
}

// ---------------- gamma-scale W -> fp16 ----------------
__global__ void wg_kernel(const float* __restrict__ W, const float* __restrict__ gamma) {
    size_t i = (size_t)blockIdx.x * 256 + threadIdx.x;   // over 737280 float4s
    float4 w = ((const float4*)W)[i];
    int k = (int)(i / 192);                              // 192 float4 per K-row
    float g = gamma[k];
    __half2 h0 = __floats2half2_rn(w.x * g, w.y * g);
    __half2 h1 = __floats2half2_rn(w.z * g, w.w * g);
    ((__half2*)g_Wh)[i * 2]     = h0;
    ((__half2*)g_Wh)[i * 2 + 1] = h1;
}

// ---------------- GEMM (fp16 mma.sync m16n8k16 + ldmatrix, 4-stage) ----------------
#define BM 128
#define BN 256
#define BK 32
#define KITERS 120
#define STAGES 4
#define LDA_H 40      // halves per A row (80B)
#define LDB_H 264     // halves per B row (528B)
#define SA_BYTES (BM * LDA_H * 2)     // 10240
#define SB_BYTES (BK * LDB_H * 2)     // 16896
#define STAGE_BYTES (SA_BYTES + SB_BYTES)
#define SMEM_BYTES (STAGES * STAGE_BYTES)    // 108544

__device__ __forceinline__ uint32_t sptr(const void* p) {
    uint32_t a;
    asm("{ .reg .u64 t; cvta.to.shared.u64 t, %1; cvt.u32.u64 %0, t; }" : "=r"(a) : "l"(p));
    return a;
}
#define CP16(dst_u32, src) asm volatile("cp.async.cg.shared.global [%0], [%1], 16;" :: "r"(dst_u32), "l"(src))

#define LDSM4(r0, r1, r2, r3, a) \
    asm volatile("ldmatrix.sync.aligned.m8n8.x4.shared.b16 {%0,%1,%2,%3}, [%4];" \
                 : "=r"(r0), "=r"(r1), "=r"(r2), "=r"(r3) : "r"(a))
#define LDSM4T(r0, r1, r2, r3, a) \
    asm volatile("ldmatrix.sync.aligned.m8n8.x4.trans.shared.b16 {%0,%1,%2,%3}, [%4];" \
                 : "=r"(r0), "=r"(r1), "=r"(r2), "=r"(r3) : "r"(a))

#define MMA16(C, A_, b0_, b1_) \
    asm volatile("mma.sync.aligned.m16n8k16.row.col.f32.f16.f16.f32 " \
                 "{%0,%1,%2,%3},{%4,%5,%6,%7},{%8,%9},{%0,%1,%2,%3};" \
                 : "+f"((C)[0]), "+f"((C)[1]), "+f"((C)[2]), "+f"((C)[3]) \
                 : "r"((A_)[0]), "r"((A_)[1]), "r"((A_)[2]), "r"((A_)[3]), \
                   "r"(b0_), "r"(b1_))

__global__ __launch_bounds__(256, 1)
void gemm_kernel(const float* __restrict__ bbias, float* __restrict__ out) {
    extern __shared__ char smem[];
    const uint32_t smem_base = sptr(smem);

    const int m0 = blockIdx.x * BM;
    const int n0 = blockIdx.y * BN;
    const int t = threadIdx.x;
    const int warp = t >> 5, lane = t & 31;
    const int wm = warp >> 2, wn = warp & 3;     // warp tile: 64m x 64n
    const int gid = lane >> 2, tig = lane & 3;

    float c[4][8][4];
#pragma unroll
    for (int i = 0; i < 4; ++i)
#pragma unroll
        for (int j = 0; j < 8; ++j)
#pragma unroll
            for (int q = 0; q < 4; ++q) c[i][j][q] = 0.f;

    const __half* Ap = g_Ah + (size_t)m0 * PD;
    const __half* Bp = g_Wh + n0;

    auto load_stage = [&](int s, int it) {
        const int k0 = it * BK;
        const uint32_t sa = smem_base + s * STAGE_BYTES;
        const uint32_t sb = sa + SA_BYTES;
        // A: 128 rows x 64B = 512 chunks
#pragma unroll
        for (int q = 0; q < 2; ++q) {
            int cid = q * 256 + t;
            int row = cid >> 2, c4 = cid & 3;
            CP16(sa + row * (LDA_H * 2) + c4 * 16,
                 Ap + (size_t)row * PD + k0 + c4 * 8);
        }
        // B: 32 rows x 512B = 1024 chunks
#pragma unroll
        for (int q = 0; q < 4; ++q) {
            int cid = q * 256 + t;
            int row = cid >> 5, c16 = cid & 31;
            CP16(sb + row * (LDB_H * 2) + c16 * 16,
                 Bp + (size_t)(k0 + row) * PROJ + c16 * 8);
        }
        asm volatile("cp.async.commit_group;");
    };

    const int jmat = lane >> 3;       // 0..3: ldmatrix matrix id
    const int rrow = lane & 7;

    auto compute = [&](int s) {
        const uint32_t sa = smem_base + s * STAGE_BYTES;
        const uint32_t sb = sa + SA_BYTES;
#pragma unroll
        for (int kk = 0; kk < 2; ++kk) {
            const int kb = kk * 16;
            uint32_t af[4][4];
#pragma unroll
            for (int i = 0; i < 4; ++i) {
                int row = wm * 64 + i * 16 + (jmat & 1) * 8 + rrow;
                int col = kb + (jmat >> 1) * 8;
                LDSM4(af[i][0], af[i][1], af[i][2], af[i][3],
                      sa + row * (LDA_H * 2) + col * 2);
            }
#pragma unroll
            for (int p = 0; p < 4; ++p) {
                uint32_t b0, b1, b2, b3;
                int row = kb + (jmat & 1) * 8 + rrow;
                int col = wn * 64 + p * 16 + (jmat >> 1) * 8;
                LDSM4T(b0, b1, b2, b3, sb + row * (LDB_H * 2) + col * 2);
#pragma unroll
                for (int i = 0; i < 4; ++i) {
                    MMA16(c[i][2 * p],     af[i], b0, b1);
                    MMA16(c[i][2 * p + 1], af[i], b2, b3);
                }
            }
        }
    };

    // prologue: prefetch 3 stages (distance 3 ~ >900 cyc, covers DRAM latency)
    load_stage(0, 0);
    load_stage(1, 1);
    load_stage(2, 2);

    for (int it = 0; it < KITERS; ++it) {
        asm volatile("cp.async.wait_group 2;");   // chunk `it` resident
        __syncthreads();                          // publishes chunk it; frees slot (it+3)%4
        if (it + 3 < KITERS) load_stage((it + 3) & (STAGES - 1), it + 3);
        compute(it & (STAGES - 1));
    }

    // epilogue: token = rstd*S + (-rstd*mean)*u + (v + b)
    float ue[8][2], vb[8][2];
#pragma unroll
    for (int j = 0; j < 8; ++j) {
        int e = n0 + wn * 64 + j * 8 + tig * 2;
        ue[j][0] = g_u[e];     ue[j][1] = g_u[e + 1];
        vb[j][0] = g_v[e] + bbias[e];
        vb[j][1] = g_v[e + 1] + bbias[e + 1];
    }
#pragma unroll
    for (int i = 0; i < 4; ++i) {
        int mrow = m0 + wm * 64 + i * 16 + gid;
        float2 s0 = g_stats[mrow];
        float2 s1 = g_stats[mrow + 8];
        float r0 = s0.y, mm0 = -s0.x * s0.y;
        float r1 = s1.y, mm1 = -s1.x * s1.y;
#pragma unroll
        for (int j = 0; j < 8; ++j) {
            int e = n0 + wn * 64 + j * 8 + tig * 2;
            float* o0 = out + (size_t)mrow * PROJ + e;
            float* o1 = out + (size_t)(mrow + 8) * PROJ + e;
            o0[0] = r0 * c[i][j][0] + mm0 * ue[j][0] + vb[j][0];
            o0[1] = r0 * c[i][j][1] + mm0 * ue[j][1] + vb[j][1];
            o1[0] = r1 * c[i][j][2] + mm1 * ue[j][0] + vb[j][0];
            o1[1] = r1 * c[i][j][3] + mm1 * ue[j][1] + vb[j][1];
        }
    }
}

// ---------------- launch ----------------
extern "C" void kernel_launch(void* const* d_in, const int* in_sizes, int n_in,
                              void* d_out, int out_size) {
    const float* images = (const float*)d_in[0];
    const float* gamma  = (const float*)d_in[1];
    const float* beta   = (const float*)d_in[2];
    const float* W      = (const float*)d_in[3];
    const float* b      = (const float*)d_in[4];
    float* out = (float*)d_out;
    float* tokens  = out;
    float* patches = out + TOKN;

    patch_kernel<<<NPATCH, 256>>>(images, patches);
    zero_uv_kernel<<<1, 768>>>();
    uv_kernel<<<dim3(3, 16), 256>>>(W, gamma, beta);
    wg_kernel<<<2880, 256>>>(W, gamma);

    static bool configured = false;
    if (!configured) {
        cudaFuncSetAttribute(gemm_kernel, cudaFuncAttributeMaxDynamicSharedMemorySize, SMEM_BYTES);
        configured = true;
    }
    gemm_kernel<<<dim3(98, 3), 256, SMEM_BYTES>>>(b, tokens);
}

// round 7
// speedup vs baseline: 1.8432x; 1.0296x over previous
#include <cuda_runtime.h>
#include <cuda_fp16.h>
#include <cstdint>
#include <cstddef>

#define NPATCH 12544
#define PD     3840
#define PROJ   768
#define TOKN   9633792ULL

__device__ float2 g_stats[NPATCH];
__device__ float  g_u[PROJ];
__device__ float  g_v[PROJ];
__device__ __half g_Ah[(size_t)NPATCH * PD];   // fp16 copy of patches
__device__ __half g_Wh[(size_t)PD * PROJ];     // fp16(gamma[k] * W[k][e])

// ---------------- patch extraction + LN stats + fp16 copy ----------------
__global__ void patch_kernel(const float* __restrict__ img, float* __restrict__ patches) {
    int p = blockIdx.x;
    int b = p / 196;
    int pg = p - b * 196;
    int gy = pg / 14, gx = pg - (pg / 14) * 14;
    int t = threadIdx.x;

    float vals[15];
    float s = 0.f, ss = 0.f;
#pragma unroll
    for (int j = 0; j < 15; ++j) {
        int d = t + j * 256;
        int pix = d / 15;
        int r = d - pix * 15;
        int g = r / 3;
        int c = r - g * 3;
        int py = pix >> 4, px = pix & 15;
        int dh = (g == 0) ? 0 : ((g == 1 || g == 3) ? 8 : -8);
        int dw = (g == 0) ? 0 : ((g <= 2) ? 8 : -8);
        int h = gy * 16 + py + dh;
        int w = gx * 16 + px + dw;
        float v = 0.f;
        if ((unsigned)h < 224u && (unsigned)w < 224u)
            v = img[(((size_t)b * 224 + h) * 224 + w) * 3 + c];
        vals[j] = v;
        s += v; ss += v * v;
    }
    float*  dst  = patches + (size_t)p * PD;
    __half* dsth = g_Ah   + (size_t)p * PD;
#pragma unroll
    for (int j = 0; j < 15; ++j) {
        dst[t + j * 256]  = vals[j];
        dsth[t + j * 256] = __float2half_rn(vals[j]);
    }

#pragma unroll
    for (int o = 16; o > 0; o >>= 1) {
        s  += __shfl_xor_sync(0xffffffffu, s, o);
        ss += __shfl_xor_sync(0xffffffffu, ss, o);
    }
    __shared__ float rs[16];
    int warp = t >> 5, lane = t & 31;
    if (lane == 0) { rs[warp] = s; rs[8 + warp] = ss; }
    __syncthreads();
    if (t == 0) {
        float S = 0.f, SS = 0.f;
#pragma unroll
        for (int w2 = 0; w2 < 8; ++w2) { S += rs[w2]; SS += rs[8 + w2]; }
        float mean = S * (1.f / PD);
        float var = SS * (1.f / PD) - mean * mean;
        g_stats[p] = make_float2(mean, rsqrtf(var + 1e-6f));
    }
}

// ---------------- u/v column sums ----------------
__global__ void zero_uv_kernel() {
    int t = threadIdx.x;
    if (t < PROJ) { g_u[t] = 0.f; g_v[t] = 0.f; }
}

__global__ void uv_kernel(const float* __restrict__ W, const float* __restrict__ gamma,
                          const float* __restrict__ beta) {
    int e = blockIdx.x * 256 + threadIdx.x;
    int d0 = blockIdx.y * 240;
    float u = 0.f, v = 0.f;
#pragma unroll 4
    for (int d = d0; d < d0 + 240; ++d) {
        float w = W[(size_t)d * PROJ + e];
        u += gamma[d] * w;
        v += beta[d] * w;
    }
    atomicAdd(&g_u[e], u);
    atomicAdd(&g_v[e], v);
}

// ---------------- gamma-scale W -> fp16 ----------------
__global__ void wg_kernel(const float* __restrict__ W, const float* __restrict__ gamma) {
    size_t i = (size_t)blockIdx.x * 256 + threadIdx.x;   // over 737280 float4s
    float4 w = ((const float4*)W)[i];
    int k = (int)(i / 192);                              // 192 float4 per K-row
    float g = gamma[k];
    __half2 h0 = __floats2half2_rn(w.x * g, w.y * g);
    __half2 h1 = __floats2half2_rn(w.z * g, w.w * g);
    ((__half2*)g_Wh)[i * 2]     = h0;
    ((__half2*)g_Wh)[i * 2 + 1] = h1;
}

// ---------------- GEMM: fp16 mma.sync, 512 threads, 4-stage ----------------
#define BM 128
#define BN 256
#define BK 32
#define KITERS 120
#define STAGES 4
#define LDA_H 40      // halves per A row (80B)
#define LDB_H 264     // halves per B row (528B)
#define SA_BYTES (BM * LDA_H * 2)     // 10240
#define SB_BYTES (BK * LDB_H * 2)     // 16896
#define STAGE_BYTES (SA_BYTES + SB_BYTES)
#define SMEM_BYTES (STAGES * STAGE_BYTES)    // 108544

__device__ __forceinline__ uint32_t sptr(const void* p) {
    uint32_t a;
    asm("{ .reg .u64 t; cvta.to.shared.u64 t, %1; cvt.u32.u64 %0, t; }" : "=r"(a) : "l"(p));
    return a;
}
#define CP16(dst_u32, src) asm volatile("cp.async.cg.shared.global [%0], [%1], 16;" :: "r"(dst_u32), "l"(src))

#define LDSM4(r0, r1, r2, r3, a) \
    asm volatile("ldmatrix.sync.aligned.m8n8.x4.shared.b16 {%0,%1,%2,%3}, [%4];" \
                 : "=r"(r0), "=r"(r1), "=r"(r2), "=r"(r3) : "r"(a))
#define LDSM4T(r0, r1, r2, r3, a) \
    asm volatile("ldmatrix.sync.aligned.m8n8.x4.trans.shared.b16 {%0,%1,%2,%3}, [%4];" \
                 : "=r"(r0), "=r"(r1), "=r"(r2), "=r"(r3) : "r"(a))

#define MMA16(C, A_, b0_, b1_) \
    asm volatile("mma.sync.aligned.m16n8k16.row.col.f32.f16.f16.f32 " \
                 "{%0,%1,%2,%3},{%4,%5,%6,%7},{%8,%9},{%0,%1,%2,%3};" \
                 : "+f"((C)[0]), "+f"((C)[1]), "+f"((C)[2]), "+f"((C)[3]) \
                 : "r"((A_)[0]), "r"((A_)[1]), "r"((A_)[2]), "r"((A_)[3]), \
                   "r"(b0_), "r"(b1_))

__global__ __launch_bounds__(512, 1)
void gemm_kernel(const float* __restrict__ bbias, float* __restrict__ out) {
    extern __shared__ char smem[];
    const uint32_t smem_base = sptr(smem);

    const int m0 = blockIdx.x * BM;
    const int n0 = blockIdx.y * BN;
    const int t = threadIdx.x;
    const int warp = t >> 5, lane = t & 31;
    const int wm = warp >> 2, wn = warp & 3;     // 4x4 warp grid: 32m x 64n each
    const int gid = lane >> 2, tig = lane & 3;

    float c[2][8][4];
#pragma unroll
    for (int i = 0; i < 2; ++i)
#pragma unroll
        for (int j = 0; j < 8; ++j)
#pragma unroll
            for (int q = 0; q < 4; ++q) c[i][j][q] = 0.f;

    const __half* Ap = g_Ah + (size_t)m0 * PD;
    const __half* Bp = g_Wh + n0;

    auto load_stage = [&](int s, int it) {
        const int k0 = it * BK;
        const uint32_t sa = smem_base + s * STAGE_BYTES;
        const uint32_t sb = sa + SA_BYTES;
        // A: 128 rows x 4 chunks = 512 -> 1 per thread
        {
            int row = t >> 2, c4 = t & 3;
            CP16(sa + row * (LDA_H * 2) + c4 * 16,
                 Ap + (size_t)row * PD + k0 + c4 * 8);
        }
        // B: 32 rows x 32 chunks = 1024 -> 2 per thread
#pragma unroll
        for (int q = 0; q < 2; ++q) {
            int cid = q * 512 + t;
            int row = cid >> 5, c16 = cid & 31;
            CP16(sb + row * (LDB_H * 2) + c16 * 16,
                 Bp + (size_t)(k0 + row) * PROJ + c16 * 8);
        }
        asm volatile("cp.async.commit_group;");
    };

    const int jmat = lane >> 3;       // 0..3
    const int rrow = lane & 7;

    auto compute = [&](int s) {
        const uint32_t sa = smem_base + s * STAGE_BYTES;
        const uint32_t sb = sa + SA_BYTES;
#pragma unroll
        for (int kk = 0; kk < 2; ++kk) {
            const int kb = kk * 16;
            uint32_t af[2][4];
#pragma unroll
            for (int i = 0; i < 2; ++i) {
                int row = wm * 32 + i * 16 + (jmat & 1) * 8 + rrow;
                int col = kb + (jmat >> 1) * 8;
                LDSM4(af[i][0], af[i][1], af[i][2], af[i][3],
                      sa + row * (LDA_H * 2) + col * 2);
            }
#pragma unroll
            for (int p = 0; p < 4; ++p) {
                uint32_t b0, b1, b2, b3;
                int row = kb + (jmat & 1) * 8 + rrow;
                int col = wn * 64 + p * 16 + (jmat >> 1) * 8;
                LDSM4T(b0, b1, b2, b3, sb + row * (LDB_H * 2) + col * 2);
#pragma unroll
                for (int i = 0; i < 2; ++i) {
                    MMA16(c[i][2 * p],     af[i], b0, b1);
                    MMA16(c[i][2 * p + 1], af[i], b2, b3);
                }
            }
        }
    };

    load_stage(0, 0);
    load_stage(1, 1);
    load_stage(2, 2);

    for (int it = 0; it < KITERS; ++it) {
        asm volatile("cp.async.wait_group 2;");
        __syncthreads();
        if (it + 3 < KITERS) load_stage((it + 3) & (STAGES - 1), it + 3);
        compute(it & (STAGES - 1));
    }

    // epilogue: token = rstd*S + (-rstd*mean)*u + (v + b)
    float ue[8][2], vb[8][2];
#pragma unroll
    for (int j = 0; j < 8; ++j) {
        int e = n0 + wn * 64 + j * 8 + tig * 2;
        ue[j][0] = g_u[e];     ue[j][1] = g_u[e + 1];
        vb[j][0] = g_v[e] + bbias[e];
        vb[j][1] = g_v[e + 1] + bbias[e + 1];
    }
#pragma unroll
    for (int i = 0; i < 2; ++i) {
        int mrow = m0 + wm * 32 + i * 16 + gid;
        float2 s0 = g_stats[mrow];
        float2 s1 = g_stats[mrow + 8];
        float r0 = s0.y, mm0 = -s0.x * s0.y;
        float r1 = s1.y, mm1 = -s1.x * s1.y;
#pragma unroll
        for (int j = 0; j < 8; ++j) {
            int e = n0 + wn * 64 + j * 8 + tig * 2;
            float* o0 = out + (size_t)mrow * PROJ + e;
            float* o1 = out + (size_t)(mrow + 8) * PROJ + e;
            o0[0] = r0 * c[i][j][0] + mm0 * ue[j][0] + vb[j][0];
            o0[1] = r0 * c[i][j][1] + mm0 * ue[j][1] + vb[j][1];
            o1[0] = r1 * c[i][j][2] + mm1 * ue[j][0] + vb[j][0];
            o1[1] = r1 * c[i][j][3] + mm1 * ue[j][1] + vb[j][1];
        }
    }
}

// ---------------- launch ----------------
extern "C" void kernel_launch(void* const* d_in, const int* in_sizes, int n_in,
                              void* d_out, int out_size) {
    const float* images = (const float*)d_in[0];
    const float* gamma  = (const float*)d_in[1];
    const float* beta   = (const float*)d_in[2];
    const float* W      = (const float*)d_in[3];
    const float* b      = (const float*)d_in[4];
    float* out = (float*)d_out;
    float* tokens  = out;
    float* patches = out + TOKN;

    patch_kernel<<<NPATCH, 256>>>(images, patches);
    zero_uv_kernel<<<1, 768>>>();
    uv_kernel<<<dim3(3, 16), 256>>>(W, gamma, beta);
    wg_kernel<<<2880, 256>>>(W, gamma);

    static bool configured = false;
    if (!configured) {
        cudaFuncSetAttribute(gemm_kernel, cudaFuncAttributeMaxDynamicSharedMemorySize, SMEM_BYTES);
        configured = true;
    }
    gemm_kernel<<<dim3(98, 3), 512, SMEM_BYTES>>>(b, tokens);
}